// round 6
// baseline (speedup 1.0000x reference)
#include <cuda_runtime.h>
#include <math.h>
#include <stdint.h>

#define NB 8
#define NJ 17
#define NV 64
#define NPAIR (NB * NJ)             // 136
#define VOX (NV * NV * NV)          // 262144 elems = 1 MiB per pair
#define SPLIT 16
#define NBLOCKS (NPAIR * SPLIT)     // 2176
#define THREADS 256
#define CHUNK_ELEMS (VOX / SPLIT)   // 16384 elems = 64 KB per block
#define TILE_ELEMS 4096             // 16 KB tile
#define TILE_BYTES (TILE_ELEMS * 4)
#define NTILES (CHUNK_ELEMS / TILE_ELEMS)   // 4
#define F4_PER_TILE (TILE_ELEMS / 4 / THREADS) // 4 float4 per thread per tile

__device__ float        g_pairsum[NPAIR];
__device__ unsigned int g_cnt[NPAIR];
__device__ float        g_loss = 0.0f;
__device__ unsigned int g_pairs_done = 0;

__device__ __forceinline__ uint32_t s2u(const void* p) {
    return (uint32_t)__cvta_generic_to_shared(p);
}
__device__ __forceinline__ void mbar_init(uint32_t bar, uint32_t cnt) {
    asm volatile("mbarrier.init.shared.b64 [%0], %1;" :: "r"(bar), "r"(cnt) : "memory");
}
__device__ __forceinline__ void mbar_expect(uint32_t bar, uint32_t bytes) {
    asm volatile("mbarrier.arrive.expect_tx.shared.b64 _, [%0], %1;" :: "r"(bar), "r"(bytes) : "memory");
}
__device__ __forceinline__ void mbar_wait(uint32_t bar, uint32_t parity) {
    asm volatile(
        "{\n\t.reg .pred P;\n\t"
        "WL%=:\n\t"
        "mbarrier.try_wait.parity.acquire.cta.shared::cta.b64 P, [%0], %1;\n\t"
        "@P bra WD%=;\n\t"
        "bra WL%=;\n\t"
        "WD%=:\n\t}"
        :: "r"(bar), "r"(parity) : "memory");
}
__device__ __forceinline__ void bulk_g2s(uint32_t dst, const void* src, uint32_t bytes, uint32_t bar) {
    asm volatile(
        "cp.async.bulk.shared::cta.global.mbarrier::complete_tx::bytes [%0], [%1], %2, [%3];"
        :: "r"(dst), "l"(src), "r"(bytes), "r"(bar) : "memory");
}
__device__ __forceinline__ void fence_async_proxy() {
    asm volatile("fence.proxy.async.shared::cta;" ::: "memory");
}

__device__ __forceinline__ int grid_idx(float l, float c) {
    float norm = (l - c) * (1.0f / 1000.0f);        // box_range = 1000
    int idx = (int)floorf((norm + 1.0f) * 0.5f * (float)(NV - 1));
    idx = idx < 0 ? 0 : (idx > NV - 1 ? NV - 1 : idx);
    return idx;
}

__global__ __launch_bounds__(THREADS)
void vol_ce_loss_kernel(const float* __restrict__ vol,
                        const float* __restrict__ label,
                        const float* __restrict__ center,
                        float* __restrict__ out) {
    __shared__ __align__(128) float buf[2][TILE_ELEMS];     // 2 x 16 KB
    __shared__ __align__(8) unsigned long long mbar_store[2];

    const int blk  = blockIdx.x;
    const int pair = blk / SPLIT;
    const int part = blk % SPLIT;
    const int t    = threadIdx.x;

    const float* src = vol + (size_t)pair * VOX + (size_t)part * CHUNK_ELEMS;

    const uint32_t bar0 = s2u(&mbar_store[0]);
    const uint32_t bar1 = s2u(&mbar_store[1]);
    const uint32_t sbuf0 = s2u(&buf[0][0]);
    const uint32_t sbuf1 = s2u(&buf[1][0]);

    if (t == 0) {
        mbar_init(bar0, 1);
        mbar_init(bar1, 1);
        fence_async_proxy();
    }
    __syncthreads();

    // prime the pipeline: tiles 0 and 1 in flight
    if (t == 0) {
        mbar_expect(bar0, TILE_BYTES);
        bulk_g2s(sbuf0, src, TILE_BYTES, bar0);
        mbar_expect(bar1, TILE_BYTES);
        bulk_g2s(sbuf1, src + TILE_ELEMS, TILE_BYTES, bar1);
    }

    float s0 = 0.0f, s1 = 0.0f;
#pragma unroll
    for (int tile = 0; tile < NTILES; ++tile) {
        const int b = tile & 1;
        const uint32_t bar = b ? bar1 : bar0;
        mbar_wait(bar, (tile >> 1) & 1);

        const float4* sp = reinterpret_cast<const float4*>(buf[b]) + t;
#pragma unroll
        for (int i = 0; i < F4_PER_TILE; ++i) {
            float4 v = sp[i * THREADS];
            s0 += __expf(v.x) + __expf(v.y);
            s1 += __expf(v.z) + __expf(v.w);
        }
        __syncthreads();   // all threads done reading buf[b]

        if (t == 0 && tile + 2 < NTILES) {
            mbar_expect(bar, TILE_BYTES);
            bulk_g2s(b ? sbuf1 : sbuf0, src + (size_t)(tile + 2) * TILE_ELEMS,
                     TILE_BYTES, bar);
        }
    }
    float s = s0 + s1;

#pragma unroll
    for (int off = 16; off > 0; off >>= 1)
        s += __shfl_down_sync(0xFFFFFFFFu, s, off);

    __shared__ float sh[THREADS / 32];
    const int lane = t & 31;
    const int wid  = t >> 5;
    if (lane == 0) sh[wid] = s;
    __syncthreads();

    // ---- distributed finalize: block completing its pair computes that term ----
    if (t == 0) {
        float v = 0.0f;
#pragma unroll
        for (int k = 0; k < THREADS / 32; ++k) v += sh[k];
        atomicAdd(&g_pairsum[pair], v);
        __threadfence();
        unsigned int prev = atomicAdd(&g_cnt[pair], 1u);
        if (prev == SPLIT - 1) {
            __threadfence();
            const float S = atomicAdd(&g_pairsum[pair], 0.0f);  // coherent read

            const int bb = pair / NJ;
            const float cx = __ldg(center + bb * 3 + 0);
            const float cy = __ldg(center + bb * 3 + 1);
            const float cz = __ldg(center + bb * 3 + 2);
            const float lx = __ldg(label + pair * 3 + 0);
            const float ly = __ldg(label + pair * 3 + 1);
            const float lz = __ldg(label + pair * 3 + 2);

            const int ix = grid_idx(lx, cx);
            const int iy = grid_idx(ly, cy);
            const int iz = grid_idx(lz, cz);
            const int flat = (ix * NV + iy) * NV + iz;

            const float x = __ldg(vol + (size_t)pair * VOX + flat);
            const float pprob = __expf(x) / S;
            const float term = -logf(pprob + 1e-6f) * (0.01f / (float)NPAIR);

            g_pairsum[pair] = 0.0f;   // reset for next graph replay
            g_cnt[pair] = 0u;

            atomicAdd(&g_loss, term);
            __threadfence();
            unsigned int pd = atomicAdd(&g_pairs_done, 1u);
            if (pd == NPAIR - 1) {
                __threadfence();
                out[0] = atomicAdd(&g_loss, 0.0f);
                g_loss = 0.0f;
                g_pairs_done = 0u;
                __threadfence();
            }
        }
    }
}

extern "C" void kernel_launch(void* const* d_in, const int* in_sizes, int n_in,
                              void* d_out, int out_size) {
    const float* vol    = (const float*)d_in[0];
    const float* label  = (const float*)d_in[1];
    const float* center = (const float*)d_in[2];
    float* out = (float*)d_out;

    vol_ce_loss_kernel<<<NBLOCKS, THREADS>>>(vol, label, center, out);
}